// round 9
// baseline (speedup 1.0000x reference)
#include <cuda_runtime.h>

// LSTM_model_59244778881379 — autoregressive LSTM rollout, persistent per-CTA.
// B=8192, T=64, F=64, ORDER=16, K=256. fp32 (fma.rn.f32x2 packed FMA).
//
// R8: eliminate weight-load redundancy. One row group: each thread owns all 32
// rows x 1 unit x 4 gates (acc = 64 u64). Activations stored TRANSPOSED in smem
// (inp_sT[k][row], stride 40) so a row-pair loads as one broadcast LDS.64,
// feeding fma.rn.f32x2 with a duplicated weight. Weight traffic/k drops 4x
// (4 coalesced LDG.32/warp/k -> ~32 wavefronts/k, L1tex queue ~empty), and the
// 3-deep weight prefetch ring now actually covers bare L2 latency.

#define BATCH    8192
#define HOR      64
#define FDIM     64
#define ORD      16
#define KH       256
#define INPD     (FDIM + ORD + KH)   /* 336 */
#define KTOT     INPD
#define KSPLIT   (FDIM + ORD)        /* 80 */
#define GATE4    1024
#define MROWS    32
#define NTHREADS 256
#define STRIDE   40                  /* padded row length (floats): bank-safe, 8B-aligned pairs */
#define HOFF     (FDIM + ORD)        /* 80: h rows start */

// dynamic smem layout (floats)
#define SM_INP   0
#define SM_BIAS  (INPD * STRIDE)                 /* 13440 */
#define SM_DW    (SM_BIAS + GATE4)               /* +1024 */
#define SM_YPB   (SM_DW + KH)                    /* +256  */
#define SM_PS    (SM_YPB + MROWS * ORD)          /* +512  */
#define SM_DB    (SM_PS + 8 * 33)                /* +264  */
#define SM_TOTF  (SM_DB + 1)
#define SM_BYTES (SM_TOTF * 4)                   /* ~62 KB */

typedef unsigned long long u64;

__device__ __forceinline__ u64 ffma2(u64 a, u64 b, u64 c) {
    u64 d;
    asm("fma.rn.f32x2 %0, %1, %2, %3;" : "=l"(d) : "l"(a), "l"(b), "l"(c));
    return d;
}
__device__ __forceinline__ u64 pack2(float x) {
    u64 d;
    asm("mov.b64 %0, {%1, %1};" : "=l"(d) : "f"(x));
    return d;
}
__device__ __forceinline__ u64 pk2(float a, float b) {
    u64 d;
    asm("mov.b64 %0, {%1, %2};" : "=l"(d) : "f"(a), "f"(b));
    return d;
}
__device__ __forceinline__ float2 upk(u64 v) {
    float2 r;
    asm("mov.b64 {%0, %1}, %2;" : "=f"(r.x), "=f"(r.y) : "l"(v));
    return r;
}
__device__ __forceinline__ u64 lds64(unsigned addr) {
    u64 v;
    asm volatile("ld.shared.b64 %0, [%1];" : "=l"(v) : "r"(addr));
    return v;
}
__device__ __forceinline__ unsigned smem_u32(const void* p) {
    unsigned a;
    asm("{ .reg .u64 t; cvta.to.shared.u64 t, %1; cvt.u32.u64 %0, t; }"
        : "=r"(a) : "l"(p));
    return a;
}

__device__ __forceinline__ float sigmoidf_(float x) {
    return 1.0f / (1.0f + __expf(-x));
}

// weight row k of concatenated [Wk;Wr] for this thread's unit u0, 4 gates
__device__ __forceinline__ void loadw4(float (&w)[4], const float* __restrict__ Wk,
                                       const float* __restrict__ Wr, int k, int u0) {
    const float* p = (k < KSPLIT) ? (Wk + (size_t)k * GATE4 + u0)
                                  : (Wr + (size_t)(k - KSPLIT) * GATE4 + u0);
#pragma unroll
    for (int g = 0; g < 4; g++) w[g] = __ldg(p + g * KH);
}

// acc[g][rp] += a2(rowpair rp at column k) * w[g]   (16 pairs = 32 rows)
__device__ __forceinline__ void fmak(u64 (&acc)[4][16], const float (&w)[4],
                                     unsigned inp_addr, int k) {
    u64 wd[4];
#pragma unroll
    for (int g = 0; g < 4; g++) wd[g] = pack2(w[g]);
    unsigned base = inp_addr + (unsigned)(k * STRIDE) * 4u;
#pragma unroll
    for (int rp = 0; rp < 16; rp++) {
        u64 a2 = lds64(base + rp * 8u);     // broadcast: all lanes same addr
#pragma unroll
        for (int g = 0; g < 4; g++)
            acc[g][rp] = ffma2(a2, wd[g], acc[g][rp]);
    }
}

extern __shared__ float sm[];

__global__ void __launch_bounds__(NTHREADS, 1)
lstm_rollout(const float* __restrict__ x, const float* __restrict__ y0,
             const float* __restrict__ Wk, const float* __restrict__ Wr,
             const float* __restrict__ bias, const float* __restrict__ dw,
             const float* __restrict__ db, float* __restrict__ out)
{
    float* inp    = sm + SM_INP;    // [INPD][STRIDE], transposed: inp[k*STRIDE + row]
    float* bias_s = sm + SM_BIAS;
    float* dw_s   = sm + SM_DW;
    float* ypb    = sm + SM_YPB;    // [32][16] circular
    float* ps     = sm + SM_PS;     // [8][33]
    float* db_s   = sm + SM_DB;

    const int tid  = threadIdx.x;
    const int u0   = tid;                    // unit 0..255
    const int row0 = blockIdx.x * MROWS;
    const unsigned inp_addr = smem_u32(inp);

    // init: h region zero (rows HOFF..INPD-1 of transposed layout)
    for (int i = tid; i < (INPD - HOFF) * STRIDE; i += NTHREADS)
        inp[HOFF * STRIDE + i] = 0.0f;
    for (int i = tid; i < MROWS * ORD; i += NTHREADS) {
        int r = i >> 4, j = i & 15;
        ypb[r * ORD + j] = __ldg(y0 + (size_t)(row0 + r) * ORD + j);
    }
    for (int i = tid; i < GATE4; i += NTHREADS) bias_s[i] = __ldg(bias + i);
    if (tid < KH) dw_s[tid] = __ldg(dw + tid);
    if (tid == 0) db_s[0] = __ldg(db);
    __syncthreads();

    // per-thread bias (duplicated across the row-pair lanes)
    u64 bacc[4];
#pragma unroll
    for (int g = 0; g < 4; g++) bacc[g] = pack2(bias_s[g * KH + u0]);

    u64 c2[16];
#pragma unroll
    for (int rp = 0; rp < 16; rp++) c2[rp] = 0ull;

    int head = 0;

    for (int t = 0; t < HOR; t++) {
        // ---- stage x_t (transposed) and yp window ----
        for (int i = tid; i < MROWS * FDIM; i += NTHREADS) {
            int f = i & 63, r = i >> 6;      // lanes: consecutive f -> coalesced LDG
            inp[f * STRIDE + r] =
                __ldg(x + ((size_t)(row0 + r) * HOR + t) * FDIM + f);
        }
        for (int i = tid; i < MROWS * ORD; i += NTHREADS) {
            int r = i & 31, j = i >> 5;
            inp[(FDIM + j) * STRIDE + r] = ypb[r * ORD + ((head + j) & 15)];
        }
        __syncthreads();

        // ---- fused GEMM with 3-deep weight ring ----
        u64 acc[4][16];
#pragma unroll
        for (int g = 0; g < 4; g++)
#pragma unroll
            for (int rp = 0; rp < 16; rp++) acc[g][rp] = bacc[g];

        float w0[4], w1[4], w2[4];
        loadw4(w0, Wk, Wr, 0, u0);
        loadw4(w1, Wk, Wr, 1, u0);
#pragma unroll 1
        for (int k = 0; k < KTOT; k += 3) {          // 336 = 3*112
            loadw4(w2, Wk, Wr, k + 2, u0);
            fmak(acc, w0, inp_addr, k);
            if (k + 3 < KTOT) loadw4(w0, Wk, Wr, k + 3, u0);
            fmak(acc, w1, inp_addr, k + 1);
            if (k + 4 < KTOT) loadw4(w1, Wk, Wr, k + 4, u0);
            fmak(acc, w2, inp_addr, k + 2);
        }

        // ---- gates + state update (row-pairs, thread-local) ----
        float hv[32];
#pragma unroll
        for (int rp = 0; rp < 16; rp++) {
            float2 iv = upk(acc[0][rp]);
            float2 fv = upk(acc[1][rp]);
            float2 gv = upk(acc[2][rp]);
            float2 ov = upk(acc[3][rp]);
            float2 cc = upk(c2[rp]);
            float i0 = sigmoidf_(iv.x), i1 = sigmoidf_(iv.y);
            float f0 = sigmoidf_(fv.x), f1 = sigmoidf_(fv.y);
            float g0 = tanhf(gv.x),     g1 = tanhf(gv.y);
            float o0 = sigmoidf_(ov.x), o1 = sigmoidf_(ov.y);
            float cn0 = f0 * cc.x + i0 * g0;
            float cn1 = f1 * cc.y + i1 * g1;
            c2[rp] = pk2(cn0, cn1);
            hv[2 * rp + 0] = o0 * tanhf(cn0);
            hv[2 * rp + 1] = o1 * tanhf(cn1);
        }

        __syncthreads();   // all GEMM/yp reads of inp done before h overwrite
        {
            float* hrow = inp + (HOFF + u0) * STRIDE;
#pragma unroll
            for (int q = 0; q < 8; q++)
                *(float4*)(hrow + 4 * q) =
                    make_float4(hv[4 * q], hv[4 * q + 1], hv[4 * q + 2], hv[4 * q + 3]);
        }
        __syncthreads();   // h_t fully visible

        // ---- pred = h @ dense_w + db ----
        {
            int r = tid & 31, sl = tid >> 5;         // 32 rows x 8 unit-slices
            const float* hb = inp + (HOFF + sl * 32) * STRIDE + r;
            const float* dwb = dw_s + sl * 32;
            float s = 0.f;
#pragma unroll
            for (int u = 0; u < 32; u++)
                s += hb[u * STRIDE] * dwb[u];
            ps[sl * 33 + r] = s;
        }
        __syncthreads();
        if (tid < 32) {
            float s = db_s[0];
#pragma unroll
            for (int sl = 0; sl < 8; sl++) s += ps[sl * 33 + tid];
            out[(size_t)(row0 + tid) * HOR + t] = s;
            ypb[tid * ORD + ((head + 15) & 15)] = s;   // shift-in newest pred
        }
        head = (head + 15) & 15;
        __syncthreads();   // ypb visible before next staging
    }
}

extern "C" void kernel_launch(void* const* d_in, const int* in_sizes, int n_in,
                              void* d_out, int out_size) {
    const float* x    = (const float*)d_in[0];
    const float* y0   = (const float*)d_in[1];
    const float* Wk   = (const float*)d_in[2];   // [80, 1024]
    const float* Wr   = (const float*)d_in[3];   // [256, 1024]
    const float* bias = (const float*)d_in[4];   // [1024]
    const float* dw   = (const float*)d_in[5];   // [256, 1]
    const float* db   = (const float*)d_in[6];   // [1]
    float* out = (float*)d_out;                  // [8192, 64, 1]
    static bool attr_set = false;
    if (!attr_set) {
        cudaFuncSetAttribute(lstm_rollout,
                             cudaFuncAttributeMaxDynamicSharedMemorySize, SM_BYTES);
        attr_set = true;
    }
    lstm_rollout<<<BATCH / MROWS, NTHREADS, SM_BYTES>>>(x, y0, Wk, Wr, bias, dw, db, out);
}

// round 11
// speedup vs baseline: 1.0481x; 1.0481x over previous
#include <cuda_runtime.h>

// LSTM_model_59244778881379 — autoregressive LSTM rollout, persistent per-CTA.
// B=8192, T=64, F=64, ORDER=16, K=256. fp32 (fma.rn.f32x2 packed FMA).
//
// R8: eliminate weight-load redundancy. One row group: each thread owns all 32
// rows x 1 unit x 4 gates (acc = 64 u64). Activations stored TRANSPOSED in smem
// (inp_sT[k][row], stride 40) so a row-pair loads as one broadcast LDS.64,
// feeding fma.rn.f32x2 with a duplicated weight. Weight traffic/k drops 4x
// (4 coalesced LDG.32/warp/k -> ~32 wavefronts/k, L1tex queue ~empty), and the
// 3-deep weight prefetch ring now actually covers bare L2 latency.

#define BATCH    8192
#define HOR      64
#define FDIM     64
#define ORD      16
#define KH       256
#define INPD     (FDIM + ORD + KH)   /* 336 */
#define KTOT     INPD
#define KSPLIT   (FDIM + ORD)        /* 80 */
#define GATE4    1024
#define MROWS    32
#define NTHREADS 256
#define STRIDE   40                  /* padded row length (floats): bank-safe, 8B-aligned pairs */
#define HOFF     (FDIM + ORD)        /* 80: h rows start */

// dynamic smem layout (floats)
#define SM_INP   0
#define SM_BIAS  (INPD * STRIDE)                 /* 13440 */
#define SM_DW    (SM_BIAS + GATE4)               /* +1024 */
#define SM_YPB   (SM_DW + KH)                    /* +256  */
#define SM_PS    (SM_YPB + MROWS * ORD)          /* +512  */
#define SM_DB    (SM_PS + 8 * 33)                /* +264  */
#define SM_TOTF  (SM_DB + 1)
#define SM_BYTES (SM_TOTF * 4)                   /* ~62 KB */

typedef unsigned long long u64;

__device__ __forceinline__ u64 ffma2(u64 a, u64 b, u64 c) {
    u64 d;
    asm("fma.rn.f32x2 %0, %1, %2, %3;" : "=l"(d) : "l"(a), "l"(b), "l"(c));
    return d;
}
__device__ __forceinline__ u64 pack2(float x) {
    u64 d;
    asm("mov.b64 %0, {%1, %1};" : "=l"(d) : "f"(x));
    return d;
}
__device__ __forceinline__ u64 pk2(float a, float b) {
    u64 d;
    asm("mov.b64 %0, {%1, %2};" : "=l"(d) : "f"(a), "f"(b));
    return d;
}
__device__ __forceinline__ float2 upk(u64 v) {
    float2 r;
    asm("mov.b64 {%0, %1}, %2;" : "=f"(r.x), "=f"(r.y) : "l"(v));
    return r;
}
__device__ __forceinline__ u64 lds64(unsigned addr) {
    u64 v;
    asm volatile("ld.shared.b64 %0, [%1];" : "=l"(v) : "r"(addr));
    return v;
}
__device__ __forceinline__ unsigned smem_u32(const void* p) {
    unsigned a;
    asm("{ .reg .u64 t; cvta.to.shared.u64 t, %1; cvt.u32.u64 %0, t; }"
        : "=r"(a) : "l"(p));
    return a;
}

__device__ __forceinline__ float sigmoidf_(float x) {
    return 1.0f / (1.0f + __expf(-x));
}

// weight row k of concatenated [Wk;Wr] for this thread's unit u0, 4 gates
__device__ __forceinline__ void loadw4(float (&w)[4], const float* __restrict__ Wk,
                                       const float* __restrict__ Wr, int k, int u0) {
    const float* p = (k < KSPLIT) ? (Wk + (size_t)k * GATE4 + u0)
                                  : (Wr + (size_t)(k - KSPLIT) * GATE4 + u0);
#pragma unroll
    for (int g = 0; g < 4; g++) w[g] = __ldg(p + g * KH);
}

// acc[g][rp] += a2(rowpair rp at column k) * w[g]   (16 pairs = 32 rows)
__device__ __forceinline__ void fmak(u64 (&acc)[4][16], const float (&w)[4],
                                     unsigned inp_addr, int k) {
    u64 wd[4];
#pragma unroll
    for (int g = 0; g < 4; g++) wd[g] = pack2(w[g]);
    unsigned base = inp_addr + (unsigned)(k * STRIDE) * 4u;
#pragma unroll
    for (int rp = 0; rp < 16; rp++) {
        u64 a2 = lds64(base + rp * 8u);     // broadcast: all lanes same addr
#pragma unroll
        for (int g = 0; g < 4; g++)
            acc[g][rp] = ffma2(a2, wd[g], acc[g][rp]);
    }
}

extern __shared__ float sm[];

__global__ void __launch_bounds__(NTHREADS, 1)
lstm_rollout(const float* __restrict__ x, const float* __restrict__ y0,
             const float* __restrict__ Wk, const float* __restrict__ Wr,
             const float* __restrict__ bias, const float* __restrict__ dw,
             const float* __restrict__ db, float* __restrict__ out)
{
    float* inp    = sm + SM_INP;    // [INPD][STRIDE], transposed: inp[k*STRIDE + row]
    float* bias_s = sm + SM_BIAS;
    float* dw_s   = sm + SM_DW;
    float* ypb    = sm + SM_YPB;    // [32][16] circular
    float* ps     = sm + SM_PS;     // [8][33]
    float* db_s   = sm + SM_DB;

    const int tid  = threadIdx.x;
    const int u0   = tid;                    // unit 0..255
    const int row0 = blockIdx.x * MROWS;
    const unsigned inp_addr = smem_u32(inp);

    // init: h region zero (rows HOFF..INPD-1 of transposed layout)
    for (int i = tid; i < (INPD - HOFF) * STRIDE; i += NTHREADS)
        inp[HOFF * STRIDE + i] = 0.0f;
    for (int i = tid; i < MROWS * ORD; i += NTHREADS) {
        int r = i >> 4, j = i & 15;
        ypb[r * ORD + j] = __ldg(y0 + (size_t)(row0 + r) * ORD + j);
    }
    for (int i = tid; i < GATE4; i += NTHREADS) bias_s[i] = __ldg(bias + i);
    if (tid < KH) dw_s[tid] = __ldg(dw + tid);
    if (tid == 0) db_s[0] = __ldg(db);
    __syncthreads();

    // per-thread bias (duplicated across the row-pair lanes)
    u64 bacc[4];
#pragma unroll
    for (int g = 0; g < 4; g++) bacc[g] = pack2(bias_s[g * KH + u0]);

    u64 c2[16];
#pragma unroll
    for (int rp = 0; rp < 16; rp++) c2[rp] = 0ull;

    int head = 0;

    for (int t = 0; t < HOR; t++) {
        // ---- stage x_t (transposed) and yp window ----
        for (int i = tid; i < MROWS * FDIM; i += NTHREADS) {
            int f = i & 63, r = i >> 6;      // lanes: consecutive f -> coalesced LDG
            inp[f * STRIDE + r] =
                __ldg(x + ((size_t)(row0 + r) * HOR + t) * FDIM + f);
        }
        for (int i = tid; i < MROWS * ORD; i += NTHREADS) {
            int r = i & 31, j = i >> 5;
            inp[(FDIM + j) * STRIDE + r] = ypb[r * ORD + ((head + j) & 15)];
        }
        __syncthreads();

        // ---- fused GEMM with 3-deep weight ring ----
        u64 acc[4][16];
#pragma unroll
        for (int g = 0; g < 4; g++)
#pragma unroll
            for (int rp = 0; rp < 16; rp++) acc[g][rp] = bacc[g];

        float w0[4], w1[4], w2[4];
        loadw4(w0, Wk, Wr, 0, u0);
        loadw4(w1, Wk, Wr, 1, u0);
#pragma unroll 1
        for (int k = 0; k < KTOT; k += 3) {          // 336 = 3*112
            loadw4(w2, Wk, Wr, k + 2, u0);
            fmak(acc, w0, inp_addr, k);
            if (k + 3 < KTOT) loadw4(w0, Wk, Wr, k + 3, u0);
            fmak(acc, w1, inp_addr, k + 1);
            if (k + 4 < KTOT) loadw4(w1, Wk, Wr, k + 4, u0);
            fmak(acc, w2, inp_addr, k + 2);
        }

        // ---- gates + state update (row-pairs, thread-local) ----
        float hv[32];
#pragma unroll
        for (int rp = 0; rp < 16; rp++) {
            float2 iv = upk(acc[0][rp]);
            float2 fv = upk(acc[1][rp]);
            float2 gv = upk(acc[2][rp]);
            float2 ov = upk(acc[3][rp]);
            float2 cc = upk(c2[rp]);
            float i0 = sigmoidf_(iv.x), i1 = sigmoidf_(iv.y);
            float f0 = sigmoidf_(fv.x), f1 = sigmoidf_(fv.y);
            float g0 = tanhf(gv.x),     g1 = tanhf(gv.y);
            float o0 = sigmoidf_(ov.x), o1 = sigmoidf_(ov.y);
            float cn0 = f0 * cc.x + i0 * g0;
            float cn1 = f1 * cc.y + i1 * g1;
            c2[rp] = pk2(cn0, cn1);
            hv[2 * rp + 0] = o0 * tanhf(cn0);
            hv[2 * rp + 1] = o1 * tanhf(cn1);
        }

        __syncthreads();   // all GEMM/yp reads of inp done before h overwrite
        {
            float* hrow = inp + (HOFF + u0) * STRIDE;
#pragma unroll
            for (int q = 0; q < 8; q++)
                *(float4*)(hrow + 4 * q) =
                    make_float4(hv[4 * q], hv[4 * q + 1], hv[4 * q + 2], hv[4 * q + 3]);
        }
        __syncthreads();   // h_t fully visible

        // ---- pred = h @ dense_w + db ----
        {
            int r = tid & 31, sl = tid >> 5;         // 32 rows x 8 unit-slices
            const float* hb = inp + (HOFF + sl * 32) * STRIDE + r;
            const float* dwb = dw_s + sl * 32;
            float s = 0.f;
#pragma unroll
            for (int u = 0; u < 32; u++)
                s += hb[u * STRIDE] * dwb[u];
            ps[sl * 33 + r] = s;
        }
        __syncthreads();
        if (tid < 32) {
            float s = db_s[0];
#pragma unroll
            for (int sl = 0; sl < 8; sl++) s += ps[sl * 33 + tid];
            out[(size_t)(row0 + tid) * HOR + t] = s;
            ypb[tid * ORD + ((head + 15) & 15)] = s;   // shift-in newest pred
        }
        head = (head + 15) & 15;
        __syncthreads();   // ypb visible before next staging
    }
}

extern "C" void kernel_launch(void* const* d_in, const int* in_sizes, int n_in,
                              void* d_out, int out_size) {
    const float* x    = (const float*)d_in[0];
    const float* y0   = (const float*)d_in[1];
    const float* Wk   = (const float*)d_in[2];   // [80, 1024]
    const float* Wr   = (const float*)d_in[3];   // [256, 1024]
    const float* bias = (const float*)d_in[4];   // [1024]
    const float* dw   = (const float*)d_in[5];   // [256, 1]
    const float* db   = (const float*)d_in[6];   // [1]
    float* out = (float*)d_out;                  // [8192, 64, 1]
    static bool attr_set = false;
    if (!attr_set) {
        cudaFuncSetAttribute(lstm_rollout,
                             cudaFuncAttributeMaxDynamicSharedMemorySize, SM_BYTES);
        attr_set = true;
    }
    lstm_rollout<<<BATCH / MROWS, NTHREADS, SM_BYTES>>>(x, y0, Wk, Wr, bias, dw, db, out);
}

// round 13
// speedup vs baseline: 2.6711x; 2.5485x over previous
#include <cuda_runtime.h>
#include <cstdint>

// R12: mma.sync tf32 LSTM rollout (tcgen05 unavailable: harness PTX target is
// compute_103 baseline). 128 persistent CTAs x 64 rows. Per step:
// z[64x1024] = A[64x336] @ W via mma.sync.m16n8k8.tf32, 8 N-tiles of 128 cols.
// Weights pre-permuted ([i,f]/[g,o] subtile interleave) + tf32-rounded by prep
// kernel; streamed with cp.async double-buffered 56k-slabs. c in smem, h via
// global scratch, yp + dense dot in registers.

#define HOR 64
#define FDIM 64
#define ORD 16
#define KH 256
#define KTOT 336
#define MROWS 64
#define NCTAS 128
#define NTHREADS 256
#define NTILES 8
#define ASTR 340              /* A row stride (floats): conflict-free frags */
#define BSTR 136              /* B slab row stride (floats): conflict-free  */
#define SLABK 56
#define NSLB 6                /* 336/56 */
#define SLABB (SLABK*BSTR*4)  /* 30464 B */

// smem byte offsets
#define SA 0                  /* A: 64*340*4      = 87040  */
#define SB 87040              /* B: 2*30464       = 60928  */
#define SC 147968             /* c: 256*65*4      = 66560  */
#define SBIAS 214528          /* bias: 1024*4     = 4096   */
#define SDW 218624            /* dw: 256*4        = 1024   */
#define SDOT 219648           /* dot: 128*4       = 512    */
#define SMEM_TOTAL 220160

__device__ __align__(16) unsigned W_img[(size_t)NTILES*KTOT*BSTR]; // 1.46 MB tf32 bits
__device__ float bias_img[NTILES*128];
__device__ float h_glob[(size_t)NCTAS*KH*MROWS];                   // 8 MB

static __device__ __forceinline__ unsigned tf32r(float x){
    unsigned b; asm("cvt.rna.tf32.f32 %0, %1;" : "=r"(b) : "f"(x)); return b;
}
static __device__ __forceinline__ float sig_(float x){ return 1.0f/(1.0f+__expf(-x)); }
static __device__ __forceinline__ float th_(float x){ return 1.0f - 2.0f/(__expf(2.0f*x)+1.0f); }
static __device__ __forceinline__ unsigned smem_u32(const void* p){
    unsigned a; asm("{ .reg .u64 t; cvta.to.shared.u64 t, %1; cvt.u32.u64 %0, t; }"
                    : "=r"(a) : "l"(p)); return a;
}
static __device__ __forceinline__ void mma8(float* d, unsigned a0,unsigned a1,unsigned a2,unsigned a3,
                                            unsigned b0,unsigned b1){
    asm volatile("mma.sync.aligned.m16n8k8.row.col.f32.tf32.tf32.f32 "
        "{%0,%1,%2,%3}, {%4,%5,%6,%7}, {%8,%9}, {%0,%1,%2,%3};"
        : "+f"(d[0]),"+f"(d[1]),"+f"(d[2]),"+f"(d[3])
        : "r"(a0),"r"(a1),"r"(a2),"r"(a3),"r"(b0),"r"(b1));
}

// Permute + tf32-round weights into W_img[n][k][c]:
// col c: j=c>>3 (subtile), p=c&7; unit = 4*(j>>1)+(p>>1); gate = 2*(j&1)+(p&1)
// source col = gate*256 + n*32 + unit.  (j even: [i,f]x4u, j odd: [g,o]x4u)
__global__ void prep(const float* __restrict__ Wk, const float* __restrict__ Wr,
                     const float* __restrict__ bias){
    int b = blockIdx.x;
    int n = b / KTOT, k = b % KTOT, c = threadIdx.x;
    unsigned v = 0u; int col = 0;
    if (c < 128) {
        int j = c >> 3, p = c & 7;
        int u = 4*(j>>1) + (p>>1);
        int g = 2*(j&1) + (p&1);
        col = g*256 + n*32 + u;
        float w = (k < 80) ? Wk[(size_t)k*1024 + col] : Wr[(size_t)(k-80)*1024 + col];
        v = tf32r(w);
    }
    W_img[((size_t)n*KTOT + k)*BSTR + c] = v;
    if (k == 0 && c < 128) bias_img[n*128 + c] = bias[col];
}

extern __shared__ char smc[];

__global__ void __launch_bounds__(NTHREADS,1)
lstm_mma(const float* __restrict__ x, const float* __restrict__ y0,
         const float* __restrict__ dw, const float* __restrict__ db,
         float* __restrict__ out)
{
    const int tid = threadIdx.x, lane = tid & 31, wid = tid >> 5;
    const int mw = wid >> 1, nw = wid & 1;     // 4 M-warps x 2 N-warps
    const int R0 = mw * 16;
    const int qr = lane >> 2, qq = lane & 3;
    const int cta = blockIdx.x, row0 = cta * MROWS;

    unsigned* A   = (unsigned*)(smc + SA);
    unsigned* Bb  = (unsigned*)(smc + SB);
    float* cs     = (float*)(smc + SC);       // [256 units][65]
    float* bias_s = (float*)(smc + SBIAS);
    float* dw_s   = (float*)(smc + SDW);
    float* dotb   = (float*)(smc + SDOT);     // [2][64]
    const unsigned sbB = smem_u32(Bb);
    float* hg = h_glob + (size_t)cta * KH * MROWS;

    for (int i = tid; i < 256*65; i += NTHREADS) cs[i] = 0.f;
    for (int i = tid; i < NTILES*128; i += NTHREADS) bias_s[i] = bias_img[i];
    if (tid < KH) dw_s[tid] = __ldg(dw + tid);
    const float db0 = __ldg(db);

    float ypr[ORD];
    if (tid < MROWS) {
#pragma unroll
        for (int j = 0; j < ORD; j++) ypr[j] = __ldg(y0 + (size_t)(row0+tid)*ORD + j);
    }
    __syncthreads();

    for (int t = 0; t < HOR; t++) {
        // ---- stage A (tf32): x k0-63, yp 64-79, h 80-335 ----
#pragma unroll
        for (int i = 0; i < 16; i++) {
            int e = i*NTHREADS + tid, r = e >> 6, k = e & 63;
            A[r*ASTR + k] = tf32r(__ldg(x + ((size_t)(row0+r)*HOR + t)*FDIM + k));
        }
#pragma unroll 4
        for (int i = 0; i < 64; i++) {
            int e = i*NTHREADS + tid, u = e >> 6, r = e & 63;
            float hv = (t == 0) ? 0.f : hg[u*MROWS + r];
            A[r*ASTR + 80 + u] = tf32r(hv);
        }
        if (tid < MROWS) {
#pragma unroll
            for (int j = 0; j < ORD; j++) A[tid*ASTR + 64 + j] = tf32r(ypr[j]);
        }
        __syncthreads();

        float dotp0 = 0.f, dotp1 = 0.f;

        for (int n = 0; n < NTILES; n++) {
            float acc[8][4];
#pragma unroll
            for (int j = 0; j < 8; j++)
#pragma unroll
                for (int q = 0; q < 4; q++) acc[j][q] = 0.f;

            const char* wsrc = (const char*)(W_img + (size_t)n*KTOT*BSTR);
            for (int i = tid; i < SLABB/16; i += NTHREADS)
                asm volatile("cp.async.cg.shared.global [%0], [%1], 16;"
                    :: "r"(sbB + i*16), "l"(wsrc + i*16) : "memory");
            asm volatile("cp.async.commit_group;" ::: "memory");

            for (int s = 0; s < NSLB; s++) {
                if (s + 1 < NSLB) {
                    const char* sp2 = wsrc + (size_t)(s+1)*SLABB;
                    unsigned dst = sbB + ((s+1)&1)*SLABB;
                    for (int i = tid; i < SLABB/16; i += NTHREADS)
                        asm volatile("cp.async.cg.shared.global [%0], [%1], 16;"
                            :: "r"(dst + i*16), "l"(sp2 + i*16) : "memory");
                    asm volatile("cp.async.commit_group;" ::: "memory");
                    asm volatile("cp.async.wait_group 1;" ::: "memory");
                } else {
                    asm volatile("cp.async.wait_group 0;" ::: "memory");
                }
                __syncthreads();
                const unsigned* Bp = Bb + (s&1)*(SLABB/4);
#pragma unroll
                for (int kk = 0; kk < SLABK/8; kk++) {
                    const int ka = s*SLABK + kk*8;
                    unsigned a0 = A[(R0+qr)  *ASTR + ka + qq];
                    unsigned a1 = A[(R0+qr+8)*ASTR + ka + qq];
                    unsigned a2 = A[(R0+qr)  *ASTR + ka + qq + 4];
                    unsigned a3 = A[(R0+qr+8)*ASTR + ka + qq + 4];
#pragma unroll
                    for (int j = 0; j < 8; j++) {
                        unsigned b0 = Bp[(kk*8+qq)  *BSTR + nw*64 + j*8 + qr];
                        unsigned b1 = Bp[(kk*8+qq+4)*BSTR + nw*64 + j*8 + qr];
                        mma8(acc[j], a0,a1,a2,a3, b0,b1);
                    }
                }
                __syncthreads();   // all warps done reading buf (s&1) before reuse
            }

            // ---- epilogue tile n: gates, c update, h writeback, dense dot ----
#pragma unroll
            for (int sp = 0; sp < 4; sp++) {
                float2 bif = *(float2*)&bias_s[n*128 + nw*64 + 16*sp + 2*qq];
                float2 bgo = *(float2*)&bias_s[n*128 + nw*64 + 16*sp + 8 + 2*qq];
                const int U = n*32 + 16*nw + 4*sp + qq;
                const int cb = U*65;
                const float dwu = dw_s[U];
                {   // row r = R0+qr
                    float zi = acc[2*sp][0] + bif.x, zf = acc[2*sp][1] + bif.y;
                    float zg = acc[2*sp+1][0] + bgo.x, zo = acc[2*sp+1][1] + bgo.y;
                    float cn = sig_(zf)*cs[cb + R0+qr] + sig_(zi)*th_(zg);
                    cs[cb + R0+qr] = cn;
                    float h = sig_(zo)*th_(cn);
                    hg[U*MROWS + R0+qr] = h;
                    dotp0 += h*dwu;
                }
                {   // row r+8
                    float zi = acc[2*sp][2] + bif.x, zf = acc[2*sp][3] + bif.y;
                    float zg = acc[2*sp+1][2] + bgo.x, zo = acc[2*sp+1][3] + bgo.y;
                    float cn = sig_(zf)*cs[cb + R0+qr+8] + sig_(zi)*th_(zg);
                    cs[cb + R0+qr+8] = cn;
                    float h = sig_(zo)*th_(cn);
                    hg[U*MROWS + R0+qr+8] = h;
                    dotp1 += h*dwu;
                }
            }
        }

        // ---- dense reduce: quad shfl, cross-N-warp via smem ----
        dotp0 += __shfl_xor_sync(0xffffffffu, dotp0, 1);
        dotp0 += __shfl_xor_sync(0xffffffffu, dotp0, 2);
        dotp1 += __shfl_xor_sync(0xffffffffu, dotp1, 1);
        dotp1 += __shfl_xor_sync(0xffffffffu, dotp1, 2);
        if (qq == 0) {
            dotb[nw*MROWS + R0 + qr]     = dotp0;
            dotb[nw*MROWS + R0 + qr + 8] = dotp1;
        }
        __syncthreads();
        if (tid < MROWS) {
            float p = dotb[tid] + dotb[MROWS + tid] + db0;
            out[(size_t)(row0+tid)*HOR + t] = p;
#pragma unroll
            for (int j = ORD-1; j > 0; j--) ypr[j] = ypr[j-1];
            ypr[0] = p;
        }
        __syncthreads();   // dotb/h_glob settled before next staging
    }
}

extern "C" void kernel_launch(void* const* d_in, const int* in_sizes, int n_in,
                              void* d_out, int out_size) {
    const float* x    = (const float*)d_in[0];
    const float* y0   = (const float*)d_in[1];
    const float* Wk   = (const float*)d_in[2];   // [80, 1024]
    const float* Wr   = (const float*)d_in[3];   // [256, 1024]
    const float* bias = (const float*)d_in[4];   // [1024]
    const float* dw   = (const float*)d_in[5];   // [256, 1]
    const float* db   = (const float*)d_in[6];   // [1]
    float* out = (float*)d_out;                  // [8192, 64, 1]
    cudaFuncSetAttribute(lstm_mma, cudaFuncAttributeMaxDynamicSharedMemorySize, SMEM_TOTAL);
    prep<<<NTILES*KTOT, 136>>>(Wk, Wr, bias);
    lstm_mma<<<NCTAS, NTHREADS, SMEM_TOTAL>>>(x, y0, dw, db, out);
}

// round 14
// speedup vs baseline: 2.9152x; 1.0914x over previous
#include <cuda_runtime.h>
#include <cstdint>

// R13: mma.sync tf32 LSTM + ldmatrix fragments + 512 threads + cross-tile
// cp.async pipelining. 128 persistent CTAs x 64 rows.
// Warp grid: 4 M-warps (16 rows) x 4 N-warps (32 cols). Per k8-chunk per warp:
// 1 LDSM.x4 (A frag) + 2 LDSM.x4 (B frags, 2 j-subtiles each) + 4 MMA
// (was 20 scalar LDS + 8 MMA at 256 threads). B image [tile][slab][col][k60]
// (stride 60 floats -> conflict-free ldmatrix rows), prepped+tf32-rounded once.

#define HOR 64
#define FDIM 64
#define ORD 16
#define KH 256
#define KTOT 336
#define MROWS 64
#define NCTAS 128
#define NTHREADS 512
#define NTILES 8
#define ASTR 340              /* A row stride (floats) */
#define BSTRK 60              /* B col stride in slab (floats): 56 data + 4 pad */
#define SLABK 56
#define NSLB 6
#define SLABB (128*BSTRK*4)   /* 30720 B */

// smem byte offsets
#define SA 0                  /* A: 64*340*4 = 87040 */
#define SB 87040              /* B: 2*30720  = 61440 */
#define SC 148480             /* c: 256*65*4 = 66560 */
#define SBIAS 215040          /* 1024*4 */
#define SDW 219136            /* 256*4  */
#define SDOT 220160           /* 4*64*4 */
#define SMEM_TOTAL 221184

__device__ __align__(16) unsigned W_img[(size_t)NTILES*NSLB*128*BSTRK]; // 1.47 MB
__device__ float bias_img[NTILES*128];
__device__ float h_glob[(size_t)NCTAS*KH*MROWS];                        // 8 MB

static __device__ __forceinline__ unsigned tf32r(float x){
    unsigned b; asm("cvt.rna.tf32.f32 %0, %1;" : "=r"(b) : "f"(x)); return b;
}
static __device__ __forceinline__ float sig_(float x){ return 1.0f/(1.0f+__expf(-x)); }
static __device__ __forceinline__ float th_(float x){ return 1.0f - 2.0f/(__expf(2.0f*x)+1.0f); }
static __device__ __forceinline__ unsigned smem_u32(const void* p){
    unsigned a; asm("{ .reg .u64 t; cvta.to.shared.u64 t, %1; cvt.u32.u64 %0, t; }"
                    : "=r"(a) : "l"(p)); return a;
}
static __device__ __forceinline__ void mma8(float* d, unsigned a0,unsigned a1,unsigned a2,unsigned a3,
                                            unsigned b0,unsigned b1){
    asm volatile("mma.sync.aligned.m16n8k8.row.col.f32.tf32.tf32.f32 "
        "{%0,%1,%2,%3}, {%4,%5,%6,%7}, {%8,%9}, {%0,%1,%2,%3};"
        : "+f"(d[0]),"+f"(d[1]),"+f"(d[2]),"+f"(d[3])
        : "r"(a0),"r"(a1),"r"(a2),"r"(a3),"r"(b0),"r"(b1));
}
static __device__ __forceinline__ void ldsm4(unsigned& r0,unsigned& r1,unsigned& r2,unsigned& r3,
                                             unsigned a){
    asm volatile("ldmatrix.sync.aligned.m8n8.x4.shared.b16 {%0,%1,%2,%3}, [%4];"
        : "=r"(r0),"=r"(r1),"=r"(r2),"=r"(r3) : "r"(a));
}

// W_img[n][s][c][k60]: col c (0..127): jj=c>>3, p=c&7; unit=4*(jj>>1)+(p>>1),
// gate=2*(jj&1)+(p&1); src col = gate*256 + n*32 + unit. tf32-rounded.
__global__ void prep(const float* __restrict__ Wk, const float* __restrict__ Wr,
                     const float* __restrict__ bias){
    int b = blockIdx.x;                 // 0..47
    int n = b / NSLB, s = b % NSLB;
    int c = threadIdx.x;                // 0..127
    int jj = c >> 3, p = c & 7;
    int u = 4*(jj>>1) + (p>>1);
    int g = 2*(jj&1) + (p&1);
    int col = g*256 + n*32 + u;
    unsigned* dst = W_img + ((size_t)(n*NSLB + s)*128 + c)*BSTRK;
    for (int kk = 0; kk < BSTRK; kk++) {
        float w = 0.f;
        int k = s*SLABK + kk;
        if (kk < SLABK && k < KTOT)
            w = (k < 80) ? Wk[(size_t)k*1024 + col] : Wr[(size_t)(k-80)*1024 + col];
        dst[kk] = tf32r(w);
    }
    if (s == 0) bias_img[n*128 + c] = bias[col];
}

extern __shared__ char smc[];

static __device__ __forceinline__ void cpslab(unsigned dst, const char* src, int tid){
    for (int i = tid; i < SLABB/16; i += NTHREADS)
        asm volatile("cp.async.cg.shared.global [%0], [%1], 16;"
            :: "r"(dst + i*16), "l"(src + (size_t)i*16) : "memory");
    asm volatile("cp.async.commit_group;" ::: "memory");
}

__global__ void __launch_bounds__(NTHREADS,1)
lstm_mma(const float* __restrict__ x, const float* __restrict__ y0,
         const float* __restrict__ dw, const float* __restrict__ db,
         float* __restrict__ out)
{
    const int tid = threadIdx.x, lane = tid & 31, wid = tid >> 5;
    const int mw = wid >> 2, nw = wid & 3;       // 4 M-warps x 4 N-warps
    const int R0 = mw * 16;
    const int qr = lane >> 2, qq = lane & 3;
    const int cta = blockIdx.x, row0 = cta * MROWS;

    unsigned* A   = (unsigned*)(smc + SA);
    float* cs     = (float*)(smc + SC);
    float* bias_s = (float*)(smc + SBIAS);
    float* dw_s   = (float*)(smc + SDW);
    float* dotb   = (float*)(smc + SDOT);
    const unsigned sbA = smem_u32(smc + SA);
    const unsigned sbB = smem_u32(smc + SB);
    float* hg = h_glob + (size_t)cta * KH * MROWS;

    // lane-constant ldmatrix address offsets (derived per m8n8.x4.b16 layout)
    const unsigned offA  = ((unsigned)(R0 + (lane & 15)) * ASTR + ((lane >> 4) << 2)) * 4u;
    const unsigned colloc = (lane & 7) + ((lane >> 4) << 3);
    const unsigned offB0 = (((unsigned)nw*32 + colloc) * BSTRK + ((lane >> 3) & 1) * 4) * 4u;
    const unsigned offB1 = offB0 + 16u * BSTRK * 4u;

    for (int i = tid; i < 256*65; i += NTHREADS) cs[i] = 0.f;
    for (int i = tid; i < NTILES*128; i += NTHREADS) bias_s[i] = bias_img[i];
    if (tid < KH) dw_s[tid] = __ldg(dw + tid);
    const float db0 = __ldg(db);

    float ypr[ORD];
    if (tid < MROWS) {
#pragma unroll
        for (int j = 0; j < ORD; j++) ypr[j] = __ldg(y0 + (size_t)(row0+tid)*ORD + j);
    }
    __syncthreads();

    for (int t = 0; t < HOR; t++) {
        // ---- stage A (tf32): x k0-63, yp 64-79, h 80-335 ----
#pragma unroll
        for (int i = 0; i < 8; i++) {
            int e = i*NTHREADS + tid, r = e >> 6, k = e & 63;
            A[r*ASTR + k] = tf32r(__ldg(x + ((size_t)(row0+r)*HOR + t)*FDIM + k));
        }
#pragma unroll 4
        for (int i = 0; i < 32; i++) {
            int e = i*NTHREADS + tid, u = e >> 6, r = e & 63;
            float hv = (t == 0) ? 0.f : hg[u*MROWS + r];
            A[r*ASTR + 80 + u] = tf32r(hv);
        }
        if (tid < MROWS) {
#pragma unroll
            for (int j = 0; j < ORD; j++) A[tid*ASTR + 64 + j] = tf32r(ypr[j]);
        }
        __syncthreads();

        float dotp0 = 0.f, dotp1 = 0.f;
        cpslab(sbB, (const char*)W_img, tid);           // tile0 slab0 -> buf0

        for (int n = 0; n < NTILES; n++) {
            float acc[4][4];
#pragma unroll
            for (int j = 0; j < 4; j++)
#pragma unroll
                for (int q = 0; q < 4; q++) acc[j][q] = 0.f;

            const char* wt = (const char*)W_img + (size_t)n*NSLB*SLABB;

            for (int s = 0; s < NSLB; s++) {
                if (s + 1 < NSLB)
                    cpslab(sbB + ((s+1)&1)*SLABB, wt + (size_t)(s+1)*SLABB, tid);
                else if (n + 1 < NTILES)
                    cpslab(sbB, wt + (size_t)NSLB*SLABB, tid);   // next tile slab0 -> buf0
                else
                    asm volatile("cp.async.commit_group;" ::: "memory");   // empty group
                if (n == NTILES-1 && s == NSLB-1)
                    asm volatile("cp.async.wait_group 0;" ::: "memory");
                else
                    asm volatile("cp.async.wait_group 1;" ::: "memory");
                __syncthreads();

                const unsigned bufB = sbB + (unsigned)(s&1)*SLABB;
                const unsigned ak   = sbA + offA + (unsigned)(s*SLABK)*4u;
#pragma unroll
                for (int kk = 0; kk < SLABK/8; kk++) {
                    unsigned a0,a1,a2,a3, b00,b01,b10,b11, b20,b21,b30,b31;
                    ldsm4(a0,a1,a2,a3, ak + kk*32);
                    ldsm4(b00,b01,b10,b11, bufB + offB0 + kk*32);
                    ldsm4(b20,b21,b30,b31, bufB + offB1 + kk*32);
                    mma8(acc[0], a0,a1,a2,a3, b00,b01);
                    mma8(acc[1], a0,a1,a2,a3, b10,b11);
                    mma8(acc[2], a0,a1,a2,a3, b20,b21);
                    mma8(acc[3], a0,a1,a2,a3, b30,b31);
                }
                __syncthreads();   // all warps done with buf (s&1) before reuse
            }

            // ---- epilogue tile n: gates, c update, h writeback, dense dot ----
#pragma unroll
            for (int jh = 0; jh < 2; jh++) {
                const int U  = n*32 + 4*(nw*2 + jh) + qq;
                const int bb = n*128 + (nw*4 + jh*2)*8 + 2*qq;
                const float bi = bias_s[bb],   bf = bias_s[bb+1];
                const float bg = bias_s[bb+8], bo = bias_s[bb+9];
                const float dwu = dw_s[U];
                float* cU = cs + U*65;
                float* hU = hg + U*MROWS;
                {
                    const int r = R0 + qr;
                    float zi = acc[2*jh][0]+bi, zf = acc[2*jh][1]+bf;
                    float zg = acc[2*jh+1][0]+bg, zo = acc[2*jh+1][1]+bo;
                    float cn = sig_(zf)*cU[r] + sig_(zi)*th_(zg);
                    cU[r] = cn;
                    float h = sig_(zo)*th_(cn);
                    hU[r] = h;
                    dotp0 += h*dwu;
                }
                {
                    const int r = R0 + qr + 8;
                    float zi = acc[2*jh][2]+bi, zf = acc[2*jh][3]+bf;
                    float zg = acc[2*jh+1][2]+bg, zo = acc[2*jh+1][3]+bo;
                    float cn = sig_(zf)*cU[r] + sig_(zi)*th_(zg);
                    cU[r] = cn;
                    float h = sig_(zo)*th_(cn);
                    hU[r] = h;
                    dotp1 += h*dwu;
                }
            }
        }

        // ---- dense reduce: quad shfl (over qq), then across 4 N-warps ----
        dotp0 += __shfl_xor_sync(0xffffffffu, dotp0, 1);
        dotp0 += __shfl_xor_sync(0xffffffffu, dotp0, 2);
        dotp1 += __shfl_xor_sync(0xffffffffu, dotp1, 1);
        dotp1 += __shfl_xor_sync(0xffffffffu, dotp1, 2);
        if (qq == 0) {
            dotb[nw*MROWS + R0 + qr]     = dotp0;
            dotb[nw*MROWS + R0 + qr + 8] = dotp1;
        }
        __syncthreads();
        if (tid < MROWS) {
            float p = dotb[tid] + dotb[MROWS+tid] + dotb[2*MROWS+tid] + dotb[3*MROWS+tid] + db0;
            out[(size_t)(row0+tid)*HOR + t] = p;
#pragma unroll
            for (int j = ORD-1; j > 0; j--) ypr[j] = ypr[j-1];
            ypr[0] = p;
        }
        __syncthreads();   // dotb/hg settled before next staging overwrites A
    }
}

extern "C" void kernel_launch(void* const* d_in, const int* in_sizes, int n_in,
                              void* d_out, int out_size) {
    const float* x    = (const float*)d_in[0];
    const float* y0   = (const float*)d_in[1];
    const float* Wk   = (const float*)d_in[2];   // [80, 1024]
    const float* Wr   = (const float*)d_in[3];   // [256, 1024]
    const float* bias = (const float*)d_in[4];   // [1024]
    const float* dw   = (const float*)d_in[5];   // [256, 1]
    const float* db   = (const float*)d_in[6];   // [1]
    float* out = (float*)d_out;                  // [8192, 64, 1]
    cudaFuncSetAttribute(lstm_mma, cudaFuncAttributeMaxDynamicSharedMemorySize, SMEM_TOTAL);
    prep<<<NTILES*NSLB, 128>>>(Wk, Wr, bias);
    lstm_mma<<<NCTAS, NTHREADS, SMEM_TOTAL>>>(x, y0, dw, db, out);
}

// round 15
// speedup vs baseline: 4.8895x; 1.6772x over previous
#include <cuda_runtime.h>
#include <cuda_fp16.h>
#include <cstdint>

// R14: fp16 mma (m16n8k16) LSTM rollout. 128 persistent CTAs x 64 rows.
// vs R13 (tf32 k8): weight bytes + LDSM + MMA-instr count halved (same 10-bit
// mantissa as tf32 -> same precision class); h_glob round-trip removed via
// A-image ping-pong (epilogue writes h fp16 directly into next step's A);
// one __syncthreads per slab (copy q+1 issued post-sync, overlaps MMA q).

#define HOR 64
#define FDIM 64
#define ORD 16
#define KH 256
#define KTOT 336
#define MROWS 64
#define NCTAS 128
#define NTHREADS 512
#define NTILES 8
#define NSLB 3                 /* slabs per tile */
#define SLABK 112              /* K rows per slab */
#define BSTRK 120              /* B col stride (fp16): 112 data + 8 pad */
#define ASTR2 344              /* A row stride (fp16): 336 data + 8 pad */
#define SLABB (128*BSTRK*2)    /* 30720 B */
#define ABUF  (64*ASTR2*2)     /* 44032 B */

// smem byte offsets
#define SA 0                   /* A: 2 x 44032 = 88064 */
#define SB 88064               /* B: 2 x 30720 = 61440 */
#define SC 149504              /* c: 256*65*4  = 66560 */
#define SBIAS 216064           /* 1024*4 */
#define SDW 220160             /* 256*4  */
#define SDOT 221184            /* 4*64*4 = 1024 */
#define SMEM_TOTAL 222208

__device__ __align__(16) __half W_img[(size_t)NTILES*NSLB*128*BSTRK]; // 737 KB
__device__ float bias_img[NTILES*128];

static __device__ __forceinline__ float sig_(float x){ return 1.0f/(1.0f+__expf(-x)); }
static __device__ __forceinline__ float th_(float x){ return 1.0f - 2.0f/(__expf(2.0f*x)+1.0f); }
static __device__ __forceinline__ unsigned smem_u32(const void* p){
    unsigned a; asm("{ .reg .u64 t; cvta.to.shared.u64 t, %1; cvt.u32.u64 %0, t; }"
                    : "=r"(a) : "l"(p)); return a;
}
static __device__ __forceinline__ void mma16(float* d, unsigned a0,unsigned a1,unsigned a2,unsigned a3,
                                             unsigned b0,unsigned b1){
    asm volatile("mma.sync.aligned.m16n8k16.row.col.f32.f16.f16.f32 "
        "{%0,%1,%2,%3}, {%4,%5,%6,%7}, {%8,%9}, {%0,%1,%2,%3};"
        : "+f"(d[0]),"+f"(d[1]),"+f"(d[2]),"+f"(d[3])
        : "r"(a0),"r"(a1),"r"(a2),"r"(a3),"r"(b0),"r"(b1));
}
static __device__ __forceinline__ void ldsm4(unsigned& r0,unsigned& r1,unsigned& r2,unsigned& r3,
                                             unsigned a){
    asm volatile("ldmatrix.sync.aligned.m8n8.x4.shared.b16 {%0,%1,%2,%3}, [%4];"
        : "=r"(r0),"=r"(r1),"=r"(r2),"=r"(r3) : "r"(a));
}

// W_img[n][s][c][k120]: col c: jj=c>>3, p=c&7; unit=4*(jj>>1)+(p>>1),
// gate=2*(jj&1)+(p&1); src col = gate*256 + n*32 + unit.
__global__ void prep(const float* __restrict__ Wk, const float* __restrict__ Wr,
                     const float* __restrict__ bias){
    int b = blockIdx.x;                 // 0..23
    int n = b / NSLB, s = b % NSLB;
    int c = threadIdx.x;                // 0..127
    int jj = c >> 3, p = c & 7;
    int u = 4*(jj>>1) + (p>>1);
    int g = 2*(jj&1) + (p&1);
    int col = g*256 + n*32 + u;
    __half* dst = W_img + ((size_t)(n*NSLB + s)*128 + c)*BSTRK;
    for (int kk = 0; kk < BSTRK; kk++) {
        float w = 0.f;
        int k = s*SLABK + kk;
        if (kk < SLABK && k < KTOT)
            w = (k < 80) ? Wk[(size_t)k*1024 + col] : Wr[(size_t)(k-80)*1024 + col];
        dst[kk] = __float2half_rn(w);
    }
    if (s == 0) bias_img[n*128 + c] = bias[col];
}

extern __shared__ char smc[];

static __device__ __forceinline__ void cpslab(unsigned dst, const char* src, int tid){
    for (int i = tid; i < SLABB/16; i += NTHREADS)
        asm volatile("cp.async.cg.shared.global [%0], [%1], 16;"
            :: "r"(dst + i*16), "l"(src + (size_t)i*16) : "memory");
    asm volatile("cp.async.commit_group;" ::: "memory");
}

__global__ void __launch_bounds__(NTHREADS,1)
lstm_mma(const float* __restrict__ x, const float* __restrict__ y0,
         const float* __restrict__ dw, const float* __restrict__ db,
         float* __restrict__ out)
{
    const int tid = threadIdx.x, lane = tid & 31, wid = tid >> 5;
    const int mw = wid >> 2, nw = wid & 3;       // 4 M-warps x 4 N-warps
    const int R0 = mw * 16;
    const int qr = lane >> 2, qq = lane & 3;
    const int cta = blockIdx.x, row0 = cta * MROWS;

    float* cs     = (float*)(smc + SC);
    float* bias_s = (float*)(smc + SBIAS);
    float* dw_s   = (float*)(smc + SDW);
    float* dotb   = (float*)(smc + SDOT);
    const unsigned sbA = smem_u32(smc + SA);
    const unsigned sbB = smem_u32(smc + SB);

    // ldmatrix lane offsets (halfword units -> bytes)
    const unsigned offA  = ((unsigned)(R0 + (lane & 15)) * ASTR2 + (lane >> 4) * 8u) * 2u;
    const unsigned offB0 = (((unsigned)nw*32u + (lane >> 4)*8u + (lane & 7u)) * BSTRK
                            + ((lane >> 3) & 1u) * 8u) * 2u;
    const unsigned offB1 = offB0 + 16u * BSTRK * 2u;

    for (int i = tid; i < 256*65; i += NTHREADS) cs[i] = 0.f;
    for (int i = tid; i < NTILES*128; i += NTHREADS) bias_s[i] = bias_img[i];
    if (tid < KH) dw_s[tid] = __ldg(dw + tid);
    const float db0 = __ldg(db);
    // zero h region of A buf0 (t=0 reads it)
    {
        __half2 z2 = __floats2half2_rn(0.f, 0.f);
        __half* A0 = (__half*)(smc + SA);
        for (int i = tid; i < 64*128; i += NTHREADS) {
            int r = i >> 7, u2 = i & 127;
            *(__half2*)(A0 + r*ASTR2 + 80 + 2*u2) = z2;
        }
    }
    float ypr[ORD];
    if (tid < MROWS) {
#pragma unroll
        for (int j = 0; j < ORD; j++) ypr[j] = __ldg(y0 + (size_t)(row0+tid)*ORD + j);
    }
    __syncthreads();

    for (int t = 0; t < HOR; t++) {
        __half* Ac = (__half*)(smc + SA + (t & 1)*ABUF);        // GEMM reads
        __half* An = (__half*)(smc + SA + ((t+1) & 1)*ABUF);    // epilogue h dest
        const unsigned sbAc = sbA + (unsigned)(t & 1)*ABUF;

        // ---- stage x_t (fp16 pairs) + yp into Ac ----
#pragma unroll
        for (int i = 0; i < 4; i++) {
            int e = i*NTHREADS + tid;            // 0..2047 pairs
            int r = e >> 5, kp = e & 31;
            float2 xv = *(const float2*)(x + ((size_t)(row0+r)*HOR + t)*FDIM + kp*2);
            *(__half2*)(Ac + r*ASTR2 + kp*2) = __floats2half2_rn(xv.x, xv.y);
        }
        if (tid < MROWS) {
#pragma unroll
            for (int j = 0; j < ORD/2; j++)
                *(__half2*)(Ac + tid*ASTR2 + 64 + 2*j) = __floats2half2_rn(ypr[2*j], ypr[2*j+1]);
        }
        cpslab(sbB, (const char*)W_img, tid);    // copy q=0 -> buf0
        __syncthreads();                          // staging + h(from t-1 epilogue) visible

        float dotp0 = 0.f, dotp1 = 0.f;

        for (int n = 0; n < NTILES; n++) {
            float acc[4][4];
#pragma unroll
            for (int j = 0; j < 4; j++)
#pragma unroll
                for (int q = 0; q < 4; q++) acc[j][q] = 0.f;

            for (int s = 0; s < NSLB; s++) {
                const int q = n*NSLB + s;
                asm volatile("cp.async.wait_group 0;" ::: "memory");   // copy q done
                __syncthreads();   // all warps: copy q visible, MMA q-1 finished
                if (q + 1 < NTILES*NSLB)
                    cpslab(sbB + (unsigned)((q+1)&1)*SLABB,
                           (const char*)W_img + (size_t)(q+1)*SLABB, tid);

                const unsigned bufB = sbB + (unsigned)(q & 1)*SLABB;
                const unsigned ak   = sbAc + offA + (unsigned)(s*SLABK)*2u;
#pragma unroll
                for (int kk = 0; kk < SLABK/16; kk++) {               // 7 chunks
                    unsigned a0,a1,a2,a3, b00,b01,b10,b11, b20,b21,b30,b31;
                    ldsm4(a0,a1,a2,a3, ak + kk*32);
                    ldsm4(b00,b01,b10,b11, bufB + offB0 + kk*32);
                    ldsm4(b20,b21,b30,b31, bufB + offB1 + kk*32);
                    mma16(acc[0], a0,a1,a2,a3, b00,b01);
                    mma16(acc[1], a0,a1,a2,a3, b10,b11);
                    mma16(acc[2], a0,a1,a2,a3, b20,b21);
                    mma16(acc[3], a0,a1,a2,a3, b30,b31);
                }
            }

            // ---- epilogue tile n: gates, c update, h -> An (fp16), dense dot ----
#pragma unroll
            for (int jh = 0; jh < 2; jh++) {
                const int U  = n*32 + 4*(nw*2 + jh) + qq;
                const int bb = n*128 + (nw*4 + jh*2)*8 + 2*qq;
                const float bi = bias_s[bb],   bf = bias_s[bb+1];
                const float bg = bias_s[bb+8], bo = bias_s[bb+9];
                const float dwu = dw_s[U];
                float* cU = cs + U*65;
                {
                    const int r = R0 + qr;
                    float zi = acc[2*jh][0]+bi, zf = acc[2*jh][1]+bf;
                    float zg = acc[2*jh+1][0]+bg, zo = acc[2*jh+1][1]+bo;
                    float cn = sig_(zf)*cU[r] + sig_(zi)*th_(zg);
                    cU[r] = cn;
                    float h = sig_(zo)*th_(cn);
                    An[r*ASTR2 + 80 + U] = __float2half_rn(h);
                    dotp0 += h*dwu;
                }
                {
                    const int r = R0 + qr + 8;
                    float zi = acc[2*jh][2]+bi, zf = acc[2*jh][3]+bf;
                    float zg = acc[2*jh+1][2]+bg, zo = acc[2*jh+1][3]+bo;
                    float cn = sig_(zf)*cU[r] + sig_(zi)*th_(zg);
                    cU[r] = cn;
                    float h = sig_(zo)*th_(cn);
                    An[r*ASTR2 + 80 + U] = __float2half_rn(h);
                    dotp1 += h*dwu;
                }
            }
        }

        // ---- dense reduce: quad shfl, then across 4 N-warps via smem ----
        dotp0 += __shfl_xor_sync(0xffffffffu, dotp0, 1);
        dotp0 += __shfl_xor_sync(0xffffffffu, dotp0, 2);
        dotp1 += __shfl_xor_sync(0xffffffffu, dotp1, 1);
        dotp1 += __shfl_xor_sync(0xffffffffu, dotp1, 2);
        if (qq == 0) {
            dotb[nw*MROWS + R0 + qr]     = dotp0;
            dotb[nw*MROWS + R0 + qr + 8] = dotp1;
        }
        __syncthreads();
        if (tid < MROWS) {
            float p = dotb[tid] + dotb[MROWS+tid] + dotb[2*MROWS+tid] + dotb[3*MROWS+tid] + db0;
            out[(size_t)(row0+tid)*HOR + t] = p;
#pragma unroll
            for (int j = ORD-1; j > 0; j--) ypr[j] = ypr[j-1];
            ypr[0] = p;
        }
        __syncthreads();   // h/dot settled before next staging
    }
}

extern "C" void kernel_launch(void* const* d_in, const int* in_sizes, int n_in,
                              void* d_out, int out_size) {
    const float* x    = (const float*)d_in[0];
    const float* y0   = (const float*)d_in[1];
    const float* Wk   = (const float*)d_in[2];   // [80, 1024]
    const float* Wr   = (const float*)d_in[3];   // [256, 1024]
    const float* bias = (const float*)d_in[4];   // [1024]
    const float* dw   = (const float*)d_in[5];   // [256, 1]
    const float* db   = (const float*)d_in[6];   // [1]
    float* out = (float*)d_out;                  // [8192, 64, 1]
    cudaFuncSetAttribute(lstm_mma, cudaFuncAttributeMaxDynamicSharedMemorySize, SMEM_TOTAL);
    prep<<<NTILES*NSLB, 128>>>(Wk, Wr, bias);
    lstm_mma<<<NCTAS, NTHREADS, SMEM_TOTAL>>>(x, y0, dw, db, out);
}